// round 13
// baseline (speedup 1.0000x reference)
#include <cuda_runtime.h>
#include <cstdint>

#define T_SEQ  2048
#define BATCH  8
#define DMODEL 1024
#define WIN    64
#define LOG2E  1.4426950408889634f

// Scratch (≈10 MB total)
__device__ float g_M[(size_t)BATCH * DMODEL * WIN];   // M[b][d][j]
__device__ float g_P[(size_t)BATCH * T_SEQ * WIN];    // p_t[j]*log2e per batch
__device__ float g_C[(size_t)BATCH * T_SEQ * WIN];    // coefficients of v_t
__device__ float g_bP[BATCH * WIN];                   // bias term of p

// packed f32x2 helpers
__device__ __forceinline__ void fma2(uint64_t& acc, uint64_t a, uint64_t b) {
    asm("fma.rn.f32x2 %0, %1, %2, %0;" : "+l"(acc) : "l"(a), "l"(b));
}
__device__ __forceinline__ void add2(uint64_t& a, uint64_t b) {
    asm("add.rn.f32x2 %0, %0, %1;" : "+l"(a) : "l"(b));
}
__device__ __forceinline__ float lo2(uint64_t v) {
    return __uint_as_float((uint32_t)v);
}
__device__ __forceinline__ float hi2(uint64_t v) {
    return __uint_as_float((uint32_t)(v >> 32));
}
__device__ __forceinline__ float ex2f(float x) {
    float r; asm("ex2.approx.ftz.f32 %0, %1;" : "=f"(r) : "f"(x)); return r;
}
__device__ __forceinline__ float rcpf(float x) {
    float r; asm("rcp.approx.ftz.f32 %0, %1;" : "=f"(r) : "f"(x)); return r;
}

// ---------------------------------------------------------------------------
// biasP[b][j] = sum_e wq_b[e] * w2[e] * F[b][j][e]
// ---------------------------------------------------------------------------
__global__ __launch_bounds__(256) void bias_p_kernel(
    const float* __restrict__ feat, const float* __restrict__ wqb,
    const float* __restrict__ w2)
{
    const int b = blockIdx.x;
    const int j = threadIdx.x >> 2;
    const int q = threadIdx.x & 3;
    const float* fp = feat + ((size_t)b * T_SEQ + j) * DMODEL + q * 256;
    float s = 0.f;
#pragma unroll 4
    for (int e = 0; e < 256; e += 4) {
        float4 f  = *(const float4*)(fp + e);
        float4 wb = *(const float4*)(wqb + q * 256 + e);
        float4 ww = *(const float4*)(w2 + q * 256 + e);
        s += f.x * wb.x * ww.x + f.y * wb.y * ww.y +
             f.z * wb.z * ww.z + f.w * wb.w * ww.w;
    }
    s += __shfl_xor_sync(0xffffffffu, s, 1);
    s += __shfl_xor_sync(0xffffffffu, s, 2);
    if (q == 0) g_bP[b * WIN + j] = s;
}

// ---------------------------------------------------------------------------
// k1: M[b] = wq @ (F[b,:64]*w2)^T.  Tile 128x64, K=1024.
// ---------------------------------------------------------------------------
__global__ __launch_bounds__(256) void m_kernel(
    const float* __restrict__ wq, const float* __restrict__ w2,
    const float* __restrict__ feat)
{
    __shared__ float As[16][129];
    __shared__ float Bs[16][68];
    const int b  = blockIdx.y;
    const int d0 = blockIdx.x * 128;
    const int tid = threadIdx.x;
    const int ty = tid >> 3, tx = tid & 7;
    const int r0 = ty * 4, j0 = tx * 8;

    float acc[4][8];
#pragma unroll
    for (int i = 0; i < 4; i++)
#pragma unroll
        for (int j = 0; j < 8; j++) acc[i][j] = 0.f;

    for (int e0 = 0; e0 < DMODEL; e0 += 16) {
#pragma unroll
        for (int l = 0; l < 2; l++) {
            int s = tid + l * 256;
            int r = s >> 2, kc = (s & 3) * 4;
            float4 w = *(const float4*)(wq + (size_t)(d0 + r) * DMODEL + e0 + kc);
            As[kc + 0][r] = w.x; As[kc + 1][r] = w.y;
            As[kc + 2][r] = w.z; As[kc + 3][r] = w.w;
        }
        {
            int j = tid >> 2, kc = (tid & 3) * 4;
            float4 f = *(const float4*)(feat + ((size_t)b * T_SEQ + j) * DMODEL + e0 + kc);
            float4 w = *(const float4*)(w2 + e0 + kc);
            Bs[kc + 0][j] = f.x * w.x; Bs[kc + 1][j] = f.y * w.y;
            Bs[kc + 2][j] = f.z * w.z; Bs[kc + 3][j] = f.w * w.w;
        }
        __syncthreads();
#pragma unroll
        for (int k = 0; k < 16; k++) {
            float a[4], bb[8];
            a[0] = As[k][r0]; a[1] = As[k][r0 + 1];
            a[2] = As[k][r0 + 2]; a[3] = As[k][r0 + 3];
            *(float4*)&bb[0] = *(float4*)&Bs[k][j0];
            *(float4*)&bb[4] = *(float4*)&Bs[k][j0 + 4];
#pragma unroll
            for (int i = 0; i < 4; i++)
#pragma unroll
                for (int j = 0; j < 8; j++)
                    acc[i][j] = fmaf(a[i], bb[j], acc[i][j]);
        }
        __syncthreads();
    }
#pragma unroll
    for (int i = 0; i < 4; i++) {
        float* mp = g_M + ((size_t)b * DMODEL + d0 + r0 + i) * WIN + j0;
        *(float4*)mp       = make_float4(acc[i][0], acc[i][1], acc[i][2], acc[i][3]);
        *(float4*)(mp + 4) = make_float4(acc[i][4], acc[i][5], acc[i][6], acc[i][7]);
    }
}

// ---------------------------------------------------------------------------
// k2: P[b] = (feature[b] @ M[b] + biasP) * log2e.  Tile 128x64.
// ---------------------------------------------------------------------------
__global__ __launch_bounds__(256) void p_kernel(const float* __restrict__ feat)
{
    __shared__ float As[16][129];
    __shared__ float Bs[16][68];
    const int b  = blockIdx.y;
    const int t0 = blockIdx.x * 128;
    const int tid = threadIdx.x;
    const int ty = tid >> 3, tx = tid & 7;
    const int r0 = ty * 4, j0 = tx * 8;

    float acc[4][8];
#pragma unroll
    for (int i = 0; i < 4; i++)
#pragma unroll
        for (int j = 0; j < 8; j++) acc[i][j] = 0.f;

    for (int e0 = 0; e0 < DMODEL; e0 += 16) {
#pragma unroll
        for (int l = 0; l < 2; l++) {
            int s = tid + l * 256;
            int r = s >> 2, kc = (s & 3) * 4;
            float4 w = *(const float4*)(feat + ((size_t)b * T_SEQ + t0 + r) * DMODEL + e0 + kc);
            As[kc + 0][r] = w.x; As[kc + 1][r] = w.y;
            As[kc + 2][r] = w.z; As[kc + 3][r] = w.w;
        }
        {
            int k = tid >> 4, j4 = (tid & 15) * 4;
            *(float4*)&Bs[k][j4] =
                *(const float4*)(g_M + ((size_t)b * DMODEL + e0 + k) * WIN + j4);
        }
        __syncthreads();
#pragma unroll
        for (int k = 0; k < 16; k++) {
            float a[4], bb[8];
            a[0] = As[k][r0]; a[1] = As[k][r0 + 1];
            a[2] = As[k][r0 + 2]; a[3] = As[k][r0 + 3];
            *(float4*)&bb[0] = *(float4*)&Bs[k][j0];
            *(float4*)&bb[4] = *(float4*)&Bs[k][j0 + 4];
#pragma unroll
            for (int i = 0; i < 4; i++)
#pragma unroll
                for (int j = 0; j < 8; j++)
                    acc[i][j] = fmaf(a[i], bb[j], acc[i][j]);
        }
        __syncthreads();
    }
    float bj[8];
    *(float4*)&bj[0] = *(const float4*)(g_bP + b * WIN + j0);
    *(float4*)&bj[4] = *(const float4*)(g_bP + b * WIN + j0 + 4);
#pragma unroll
    for (int i = 0; i < 4; i++) {
        float* pp = g_P + ((size_t)b * T_SEQ + t0 + r0 + i) * WIN + j0;
        *(float4*)pp = make_float4((acc[i][0] + bj[0]) * LOG2E, (acc[i][1] + bj[1]) * LOG2E,
                                   (acc[i][2] + bj[2]) * LOG2E, (acc[i][3] + bj[3]) * LOG2E);
        *(float4*)(pp + 4) = make_float4((acc[i][4] + bj[4]) * LOG2E, (acc[i][5] + bj[5]) * LOG2E,
                                         (acc[i][6] + bj[6]) * LOG2E, (acc[i][7] + bj[7]) * LOG2E);
    }
}

// ---------------------------------------------------------------------------
// k3: coefficient-space scan — 2 fused steps/iter, 256 threads (quarters).
// Thread (i,q): i = row/col 0..63, q = quarter 0..3; owns floats
// [16q,16q+16) of row i (registers) and of column i (smem).
// lane = (i&7) | (q<<3), warp = i>>3 -> quarters of a row share a warp;
// reduction = shfl_xor 8 then 16. 8 warps => 2 warps/SMSP hide stalls.
// Same two-phase / scalar-patch algebra as before.
// ---------------------------------------------------------------------------
__global__ __launch_bounds__(256, 1) void scan_kernel()
{
    __shared__ __align__(16) float p_buf[2][2][WIN];   // [parity][A/B][j]
    __shared__ __align__(16) float eA_sh[WIN];
    __shared__ __align__(16) float eB_sh[WIN];
    __shared__ __align__(16) float sB_sh[WIN];
    __shared__ __align__(16) float cnewA[WIN];
    __shared__ __align__(16) float cnewB[WIN];
    __shared__ __align__(16) float Ccs[WIN][68];       // Ccs[i][r] = C[r][i]

    const int b    = blockIdx.x;
    const int tid  = threadIdx.x;
    const int warp = tid >> 5;
    const int lane = tid & 31;
    const int q    = lane >> 3;                 // quarter 0..3
    const int i    = (lane & 7) | (warp << 3);  // row & column index 0..63
    const int rq   = q << 4;                    // own quarter start

    // C = Identity
    uint64_t CrowP[8];
#pragma unroll
    for (int k = 0; k < 8; k++) {
        int j0 = rq + 2 * k;
        float x0 = (j0     == i) ? 1.f : 0.f;
        float x1 = (j0 + 1 == i) ? 1.f : 0.f;
        CrowP[k] = ((uint64_t)__float_as_uint(x1) << 32) | __float_as_uint(x0);
    }
    for (int r = rq; r < rq + 16; r++) Ccs[i][r] = (r == i) ? 1.f : 0.f;

    // Bootstrap: slots 62,63 were "replaced" with identity rows last iter.
    if (q == 0) {
        cnewA[i] = (i == 62) ? 1.f : 0.f;
        cnewB[i] = (i == 63) ? 1.f : 0.f;
        p_buf[0][0][i] = g_P[((size_t)b * T_SEQ + WIN)     * WIN + i];
        p_buf[0][1][i] = g_P[((size_t)b * T_SEQ + WIN + 1) * WIN + i];
    }
    __syncthreads();

    float* gC = g_C + (size_t)b * T_SEQ * WIN;
    const float* gP = g_P + (size_t)b * T_SEQ * WIN;

    for (int t0 = WIN; t0 < T_SEQ; t0 += 2) {
        const int it  = (t0 - WIN) >> 1;
        const int cur = it & 1, nxt = cur ^ 1;
        const int slotPA = (t0 - 2) & (WIN - 1);
        const int slotPB = (t0 - 1) & (WIN - 1);
        const int slotA  = t0 & (WIN - 1);
        const int slotB  = (t0 + 1) & (WIN - 1);

        // ---- phase 1 ------------------------------------------------------
        float pnC = 0.f, pnD = 0.f;
        if (q == 0) {
            int tC = (t0 + 2 < T_SEQ) ? t0 + 2 : T_SEQ - 1;
            int tD = (t0 + 3 < T_SEQ) ? t0 + 3 : T_SEQ - 1;
            pnC = gP[(size_t)tC * WIN + i];
            pnD = gP[(size_t)tD * WIN + i];
        }

        // reload rows replaced last iteration (own quarter)
        if (i == slotPA) {
            const ulonglong2* cn = (const ulonglong2*)&cnewA[rq];
#pragma unroll
            for (int k = 0; k < 4; k++) {
                ulonglong2 v = cn[k];
                CrowP[2 * k] = v.x; CrowP[2 * k + 1] = v.y;
            }
        }
        if (i == slotPB) {
            const ulonglong2* cn = (const ulonglong2*)&cnewB[rq];
#pragma unroll
            for (int k = 0; k < 4; k++) {
                ulonglong2 v = cn[k];
                CrowP[2 * k] = v.x; CrowP[2 * k + 1] = v.y;
            }
        }

        // sigA = C_i . p_t0 ; sigB = C_i . p_{t0+1}  (own quarter, 2-lvl shfl)
        const ulonglong2* pa = (const ulonglong2*)&p_buf[cur][0][rq];
        const ulonglong2* pb = (const ulonglong2*)&p_buf[cur][1][rq];
        uint64_t a0 = 0, a1 = 0, b0 = 0, b1 = 0;
#pragma unroll
        for (int k = 0; k < 4; k++) {
            ulonglong2 pva = pa[k];
            ulonglong2 pvb = pb[k];
            fma2(a0, CrowP[2 * k],     pva.x);
            fma2(a1, CrowP[2 * k + 1], pva.y);
            fma2(b0, CrowP[2 * k],     pvb.x);
            fma2(b1, CrowP[2 * k + 1], pvb.y);
        }
        add2(a0, a1); add2(b0, b1);
        float sigA = lo2(a0) + hi2(a0);
        float sigB = lo2(b0) + hi2(b0);
        sigA += __shfl_xor_sync(0xffffffffu, sigA, 8);
        sigB += __shfl_xor_sync(0xffffffffu, sigB, 8);
        sigA += __shfl_xor_sync(0xffffffffu, sigA, 16);
        sigB += __shfl_xor_sync(0xffffffffu, sigB, 16);
        if (q == 0) {
            eA_sh[i] = ex2f(sigA);
            eB_sh[i] = ex2f(sigB);
            sB_sh[i] = sigB;
        }
        __syncthreads();

        // ---- phase 2 ------------------------------------------------------
        // step A sums: dA = sum eA, uA = sum eA*Ccs, SAB = sum eA*sigB
        const ulonglong2* ev = (const ulonglong2*)&eA_sh[rq];
        const ulonglong2* sv = (const ulonglong2*)&sB_sh[rq];
        const ulonglong2* cv = (const ulonglong2*)&Ccs[i][rq];
        uint64_t dacc0 = 0, dacc1 = 0, uacc0 = 0, uacc1 = 0, sacc0 = 0, sacc1 = 0;
#pragma unroll
        for (int k = 0; k < 2; k++) {
            ulonglong2 e2a = ev[2 * k];
            ulonglong2 e2b = ev[2 * k + 1];
            ulonglong2 c2a = cv[2 * k];
            ulonglong2 c2b = cv[2 * k + 1];
            ulonglong2 s2a = sv[2 * k];
            ulonglong2 s2b = sv[2 * k + 1];
            add2(dacc0, e2a.x); add2(dacc1, e2a.y);
            add2(dacc0, e2b.x); add2(dacc1, e2b.y);
            fma2(uacc0, e2a.x, c2a.x); fma2(uacc1, e2a.y, c2a.y);
            fma2(uacc0, e2b.x, c2b.x); fma2(uacc1, e2b.y, c2b.y);
            fma2(sacc0, e2a.x, s2a.x); fma2(sacc1, e2a.y, s2a.y);
            fma2(sacc0, e2b.x, s2b.x); fma2(sacc1, e2b.y, s2b.y);
        }
        add2(dacc0, dacc1); add2(uacc0, uacc1); add2(sacc0, sacc1);
        float dA  = lo2(dacc0) + hi2(dacc0);
        float uA  = lo2(uacc0) + hi2(uacc0);
        float SAB = lo2(sacc0) + hi2(sacc0);
        dA  += __shfl_xor_sync(0xffffffffu, dA, 8);
        uA  += __shfl_xor_sync(0xffffffffu, uA, 8);
        SAB += __shfl_xor_sync(0xffffffffu, SAB, 8);
        dA  += __shfl_xor_sync(0xffffffffu, dA, 16);
        uA  += __shfl_xor_sync(0xffffffffu, uA, 16);
        SAB += __shfl_xor_sync(0xffffffffu, SAB, 16);

        const float invA = rcpf(dA + 1.f);
        const float cA_i = invA * uA;
        const float ePr  = ex2f(invA * SAB);   // exp(score of cA vs p_{t0+1})

        // commit cA (same thread later re-reads it in the step-B sum)
        if ((slotA >> 4) == q) Ccs[i][slotA] = cA_i;
        const float eB_slotA = eB_sh[slotA];

        // step B sums over UPDATED Ccs (includes cA at slotA)
        const ulonglong2* ebv = (const ulonglong2*)&eB_sh[rq];
        uint64_t db0 = 0, db1 = 0, ub0 = 0, ub1 = 0;
#pragma unroll
        for (int k = 0; k < 2; k++) {
            ulonglong2 e2a = ebv[2 * k];
            ulonglong2 e2b = ebv[2 * k + 1];
            ulonglong2 c2a = ((const ulonglong2*)&Ccs[i][rq])[2 * k];
            ulonglong2 c2b = ((const ulonglong2*)&Ccs[i][rq])[2 * k + 1];
            add2(db0, e2a.x); add2(db1, e2a.y);
            add2(db0, e2b.x); add2(db1, e2b.y);
            fma2(ub0, e2a.x, c2a.x); fma2(ub1, e2a.y, c2a.y);
            fma2(ub0, e2b.x, c2b.x); fma2(ub1, e2b.y, c2b.y);
        }
        add2(db0, db1); add2(ub0, ub1);
        float dB = lo2(db0) + hi2(db0);
        float uB = lo2(ub0) + hi2(ub0);
        dB += __shfl_xor_sync(0xffffffffu, dB, 8);
        uB += __shfl_xor_sync(0xffffffffu, uB, 8);
        dB += __shfl_xor_sync(0xffffffffu, dB, 16);
        uB += __shfl_xor_sync(0xffffffffu, uB, 16);

        const float invB = rcpf(dB - eB_slotA + ePr + 1.f);
        const float cB_i = invB * (uB + (ePr - eB_slotA) * cA_i);

        if ((slotB >> 4) == q) Ccs[i][slotB] = cB_i;
        if (q == 0) {
            cnewA[i] = cA_i;
            cnewB[i] = cB_i;
            gC[(size_t)t0 * WIN + i]       = cA_i;
            gC[(size_t)(t0 + 1) * WIN + i] = cB_i;
            p_buf[nxt][0][i] = pnC;
            p_buf[nxt][1][i] = pnD;
        }
        __syncthreads();
    }
}

// ---------------------------------------------------------------------------
// k4: V[b] = C[b] (2048x64) @ F[b] (64x1024) -> d_out for t>=64.
// ---------------------------------------------------------------------------
__global__ __launch_bounds__(256) void v_kernel(
    const float* __restrict__ feat, float* __restrict__ out)
{
    __shared__ float Cst[64][68];
    __shared__ float Fs[64][64];
    const int b  = blockIdx.z;
    const int t0 = blockIdx.x * 64;
    const int d0 = blockIdx.y * 64;
    const int tid = threadIdx.x;
    const int ty = tid >> 4, tx = tid & 15;
    const int r0 = ty * 4, c0 = tx * 4;

#pragma unroll
    for (int l = 0; l < 4; l++) {
        int s = tid + l * 256;
        int r = s >> 4, j4 = (s & 15) * 4;
        float4 c = *(const float4*)(g_C + ((size_t)b * T_SEQ + t0 + r) * WIN + j4);
        Cst[j4 + 0][r] = c.x; Cst[j4 + 1][r] = c.y;
        Cst[j4 + 2][r] = c.z; Cst[j4 + 3][r] = c.w;
    }
#pragma unroll
    for (int l = 0; l < 4; l++) {
        int s = tid + l * 256;
        int j = s >> 4, c4 = (s & 15) * 4;
        *(float4*)&Fs[j][c4] =
            *(const float4*)(feat + ((size_t)b * T_SEQ + j) * DMODEL + d0 + c4);
    }
    __syncthreads();

    float acc[4][4];
#pragma unroll
    for (int i = 0; i < 4; i++)
#pragma unroll
        for (int j = 0; j < 4; j++) acc[i][j] = 0.f;

#pragma unroll 8
    for (int k = 0; k < 64; k++) {
        float a[4], bb[4];
        a[0] = Cst[k][r0]; a[1] = Cst[k][r0 + 1];
        a[2] = Cst[k][r0 + 2]; a[3] = Cst[k][r0 + 3];
        *(float4*)&bb[0] = *(float4*)&Fs[k][c0];
#pragma unroll
        for (int i = 0; i < 4; i++)
#pragma unroll
            for (int j = 0; j < 4; j++)
                acc[i][j] = fmaf(a[i], bb[j], acc[i][j]);
    }

#pragma unroll
    for (int i = 0; i < 4; i++) {
        int t = t0 + r0 + i;
        if (t >= WIN) {
            *(float4*)(out + ((size_t)b * T_SEQ + t) * DMODEL + d0 + c0) =
                make_float4(acc[i][0], acc[i][1], acc[i][2], acc[i][3]);
        }
    }
}

// ---------------------------------------------------------------------------
// k5: epilogue y = tanh(v)*f + f, LayerNorm.
// ---------------------------------------------------------------------------
__global__ __launch_bounds__(256) void ln_kernel(
    const float* __restrict__ feature, const float* __restrict__ g,
    const float* __restrict__ bt, float* __restrict__ out)
{
    const int row = blockIdx.x;
    const int t = row & (T_SEQ - 1);
    const float* fp = feature + (size_t)row * DMODEL;
    float* op = out + (size_t)row * DMODEL;
    const float* vp = (t < WIN) ? fp : op;
    const int tid = threadIdx.x;
    const int lane = tid & 31, warp = tid >> 5;

    float4 f = *(const float4*)(fp + tid * 4);
    float4 v = *(const float4*)(vp + tid * 4);
    float y0 = tanhf(v.x) * f.x + f.x;
    float y1 = tanhf(v.y) * f.y + f.y;
    float y2 = tanhf(v.z) * f.z + f.z;
    float y3 = tanhf(v.w) * f.w + f.w;

    float s  = y0 + y1 + y2 + y3;
    float ss = y0 * y0 + y1 * y1 + y2 * y2 + y3 * y3;
#pragma unroll
    for (int o = 16; o > 0; o >>= 1) {
        s  += __shfl_xor_sync(0xffffffffu, s, o);
        ss += __shfl_xor_sync(0xffffffffu, ss, o);
    }
    __shared__ float red[8][2];
    if (lane == 0) { red[warp][0] = s; red[warp][1] = ss; }
    __syncthreads();
    if (warp == 0) {
        float a = (lane < 8) ? red[lane][0] : 0.f;
        float c = (lane < 8) ? red[lane][1] : 0.f;
#pragma unroll
        for (int o = 4; o > 0; o >>= 1) {
            a += __shfl_xor_sync(0xffffffffu, a, o);
            c += __shfl_xor_sync(0xffffffffu, c, o);
        }
        if (lane == 0) { red[0][0] = a; red[0][1] = c; }
    }
    __syncthreads();
    const float mu   = red[0][0] * (1.f / DMODEL);
    const float var  = red[0][1] * (1.f / DMODEL) - mu * mu;
    const float rstd = rsqrtf(var + 1e-5f);

    float4 gg = *(const float4*)(g + tid * 4);
    float4 bb = *(const float4*)(bt + tid * 4);
    float4 o;
    o.x = (y0 - mu) * rstd * gg.x + bb.x;
    o.y = (y1 - mu) * rstd * gg.y + bb.y;
    o.z = (y2 - mu) * rstd * gg.z + bb.z;
    o.w = (y3 - mu) * rstd * gg.w + bb.w;
    *(float4*)(op + tid * 4) = o;
}

// ---------------------------------------------------------------------------
extern "C" void kernel_launch(void* const* d_in, const int* in_sizes, int n_in,
                              void* d_out, int out_size)
{
    const float* feature = (const float*)d_in[0];
    const float* wq_w    = (const float*)d_in[1];
    const float* wq_b    = (const float*)d_in[2];
    const float* w2_w    = (const float*)d_in[3];
    // d_in[4] = w2_b: cancels by softmax shift-invariance
    const float* ln_g    = (const float*)d_in[5];
    const float* ln_b    = (const float*)d_in[6];
    float* out = (float*)d_out;

    bias_p_kernel<<<BATCH, 256>>>(feature, wq_b, w2_w);
    m_kernel<<<dim3(8, BATCH), 256>>>(wq_w, w2_w, feature);
    p_kernel<<<dim3(16, BATCH), 256>>>(feature);
    scan_kernel<<<BATCH, 256>>>();
    v_kernel<<<dim3(32, 16, BATCH), 256>>>(feature, out);
    ln_kernel<<<BATCH * T_SEQ, 256>>>(feature, ln_g, ln_b, out);
}

// round 14
// speedup vs baseline: 1.0292x; 1.0292x over previous
#include <cuda_runtime.h>
#include <cstdint>

#define T_SEQ  2048
#define BATCH  8
#define DMODEL 1024
#define WIN    64
#define LOG2E  1.4426950408889634f
#define NWORK  140
#define NTILE  256    // 32 t-blocks x 8 batches

// Scratch (≈10 MB total)
__device__ float g_M[(size_t)BATCH * DMODEL * WIN];   // M[b][d][j]
__device__ float g_P[(size_t)BATCH * T_SEQ * WIN];    // p_t[j]*log2e per batch
__device__ float g_C[(size_t)BATCH * T_SEQ * WIN];    // coefficients of v_t
__device__ float g_bP[BATCH * WIN];                   // bias term of p
__device__ int   g_prog[BATCH];                       // scan progress (64-blocks done)

// packed f32x2 helpers
__device__ __forceinline__ void fma2(uint64_t& acc, uint64_t a, uint64_t b) {
    asm("fma.rn.f32x2 %0, %1, %2, %0;" : "+l"(acc) : "l"(a), "l"(b));
}
__device__ __forceinline__ void add2(uint64_t& a, uint64_t b) {
    asm("add.rn.f32x2 %0, %0, %1;" : "+l"(a) : "l"(b));
}
__device__ __forceinline__ float lo2(uint64_t v) {
    return __uint_as_float((uint32_t)v);
}
__device__ __forceinline__ float hi2(uint64_t v) {
    return __uint_as_float((uint32_t)(v >> 32));
}
__device__ __forceinline__ float ex2f(float x) {
    float r; asm("ex2.approx.ftz.f32 %0, %1;" : "=f"(r) : "f"(x)); return r;
}
__device__ __forceinline__ float rcpf(float x) {
    float r; asm("rcp.approx.ftz.f32 %0, %1;" : "=f"(r) : "f"(x)); return r;
}

// ---------------------------------------------------------------------------
// biasP[b][j] = sum_e wq_b[e] * w2[e] * F[b][j][e]   (also zeroes g_prog)
// ---------------------------------------------------------------------------
__global__ __launch_bounds__(256) void bias_p_kernel(
    const float* __restrict__ feat, const float* __restrict__ wqb,
    const float* __restrict__ w2)
{
    if (blockIdx.x == 0 && threadIdx.x < BATCH) g_prog[threadIdx.x] = 0;
    const int b = blockIdx.x;
    const int j = threadIdx.x >> 2;
    const int q = threadIdx.x & 3;
    const float* fp = feat + ((size_t)b * T_SEQ + j) * DMODEL + q * 256;
    float s = 0.f;
#pragma unroll 4
    for (int e = 0; e < 256; e += 4) {
        float4 f  = *(const float4*)(fp + e);
        float4 wb = *(const float4*)(wqb + q * 256 + e);
        float4 ww = *(const float4*)(w2 + q * 256 + e);
        s += f.x * wb.x * ww.x + f.y * wb.y * ww.y +
             f.z * wb.z * ww.z + f.w * wb.w * ww.w;
    }
    s += __shfl_xor_sync(0xffffffffu, s, 1);
    s += __shfl_xor_sync(0xffffffffu, s, 2);
    if (q == 0) g_bP[b * WIN + j] = s;
}

// ---------------------------------------------------------------------------
// k1: M[b] = wq @ (F[b,:64]*w2)^T.  Tile 128x64, K=1024.
// ---------------------------------------------------------------------------
__global__ __launch_bounds__(256) void m_kernel(
    const float* __restrict__ wq, const float* __restrict__ w2,
    const float* __restrict__ feat)
{
    __shared__ float As[16][129];
    __shared__ float Bs[16][68];
    const int b  = blockIdx.y;
    const int d0 = blockIdx.x * 128;
    const int tid = threadIdx.x;
    const int ty = tid >> 3, tx = tid & 7;
    const int r0 = ty * 4, j0 = tx * 8;

    float acc[4][8];
#pragma unroll
    for (int i = 0; i < 4; i++)
#pragma unroll
        for (int j = 0; j < 8; j++) acc[i][j] = 0.f;

    for (int e0 = 0; e0 < DMODEL; e0 += 16) {
#pragma unroll
        for (int l = 0; l < 2; l++) {
            int s = tid + l * 256;
            int r = s >> 2, kc = (s & 3) * 4;
            float4 w = *(const float4*)(wq + (size_t)(d0 + r) * DMODEL + e0 + kc);
            As[kc + 0][r] = w.x; As[kc + 1][r] = w.y;
            As[kc + 2][r] = w.z; As[kc + 3][r] = w.w;
        }
        {
            int j = tid >> 2, kc = (tid & 3) * 4;
            float4 f = *(const float4*)(feat + ((size_t)b * T_SEQ + j) * DMODEL + e0 + kc);
            float4 w = *(const float4*)(w2 + e0 + kc);
            Bs[kc + 0][j] = f.x * w.x; Bs[kc + 1][j] = f.y * w.y;
            Bs[kc + 2][j] = f.z * w.z; Bs[kc + 3][j] = f.w * w.w;
        }
        __syncthreads();
#pragma unroll
        for (int k = 0; k < 16; k++) {
            float a[4], bb[8];
            a[0] = As[k][r0]; a[1] = As[k][r0 + 1];
            a[2] = As[k][r0 + 2]; a[3] = As[k][r0 + 3];
            *(float4*)&bb[0] = *(float4*)&Bs[k][j0];
            *(float4*)&bb[4] = *(float4*)&Bs[k][j0 + 4];
#pragma unroll
            for (int i = 0; i < 4; i++)
#pragma unroll
                for (int j = 0; j < 8; j++)
                    acc[i][j] = fmaf(a[i], bb[j], acc[i][j]);
        }
        __syncthreads();
    }
#pragma unroll
    for (int i = 0; i < 4; i++) {
        float* mp = g_M + ((size_t)b * DMODEL + d0 + r0 + i) * WIN + j0;
        *(float4*)mp       = make_float4(acc[i][0], acc[i][1], acc[i][2], acc[i][3]);
        *(float4*)(mp + 4) = make_float4(acc[i][4], acc[i][5], acc[i][6], acc[i][7]);
    }
}

// ---------------------------------------------------------------------------
// k2: P[b] = (feature[b] @ M[b] + biasP) * log2e.  Tile 128x64.
// ---------------------------------------------------------------------------
__global__ __launch_bounds__(256) void p_kernel(const float* __restrict__ feat)
{
    __shared__ float As[16][129];
    __shared__ float Bs[16][68];
    const int b  = blockIdx.y;
    const int t0 = blockIdx.x * 128;
    const int tid = threadIdx.x;
    const int ty = tid >> 3, tx = tid & 7;
    const int r0 = ty * 4, j0 = tx * 8;

    float acc[4][8];
#pragma unroll
    for (int i = 0; i < 4; i++)
#pragma unroll
        for (int j = 0; j < 8; j++) acc[i][j] = 0.f;

    for (int e0 = 0; e0 < DMODEL; e0 += 16) {
#pragma unroll
        for (int l = 0; l < 2; l++) {
            int s = tid + l * 256;
            int r = s >> 2, kc = (s & 3) * 4;
            float4 w = *(const float4*)(feat + ((size_t)b * T_SEQ + t0 + r) * DMODEL + e0 + kc);
            As[kc + 0][r] = w.x; As[kc + 1][r] = w.y;
            As[kc + 2][r] = w.z; As[kc + 3][r] = w.w;
        }
        {
            int k = tid >> 4, j4 = (tid & 15) * 4;
            *(float4*)&Bs[k][j4] =
                *(const float4*)(g_M + ((size_t)b * DMODEL + e0 + k) * WIN + j4);
        }
        __syncthreads();
#pragma unroll
        for (int k = 0; k < 16; k++) {
            float a[4], bb[8];
            a[0] = As[k][r0]; a[1] = As[k][r0 + 1];
            a[2] = As[k][r0 + 2]; a[3] = As[k][r0 + 3];
            *(float4*)&bb[0] = *(float4*)&Bs[k][j0];
            *(float4*)&bb[4] = *(float4*)&Bs[k][j0 + 4];
#pragma unroll
            for (int i = 0; i < 4; i++)
#pragma unroll
                for (int j = 0; j < 8; j++)
                    acc[i][j] = fmaf(a[i], bb[j], acc[i][j]);
        }
        __syncthreads();
    }
    float bj[8];
    *(float4*)&bj[0] = *(const float4*)(g_bP + b * WIN + j0);
    *(float4*)&bj[4] = *(const float4*)(g_bP + b * WIN + j0 + 4);
#pragma unroll
    for (int i = 0; i < 4; i++) {
        float* pp = g_P + ((size_t)b * T_SEQ + t0 + r0 + i) * WIN + j0;
        *(float4*)pp = make_float4((acc[i][0] + bj[0]) * LOG2E, (acc[i][1] + bj[1]) * LOG2E,
                                   (acc[i][2] + bj[2]) * LOG2E, (acc[i][3] + bj[3]) * LOG2E);
        *(float4*)(pp + 4) = make_float4((acc[i][4] + bj[4]) * LOG2E, (acc[i][5] + bj[5]) * LOG2E,
                                         (acc[i][6] + bj[6]) * LOG2E, (acc[i][7] + bj[7]) * LOG2E);
    }
}

// ---------------------------------------------------------------------------
// fused: CTAs 0..7 = R11 scan (128 active threads) + progress publishing.
//        CTAs 8..147 = v+ln workers consuming C tiles as they become ready.
// Shared memory aliased between the roles via one pool (34.5 KB).
// ---------------------------------------------------------------------------
__global__ __launch_bounds__(256, 1) void fused_kernel(
    const float* __restrict__ feat, const float* __restrict__ lng,
    const float* __restrict__ lnb, float* __restrict__ out)
{
    __shared__ __align__(16) float pool[8832];
    const int tid = threadIdx.x;

    if (blockIdx.x < BATCH) {
        // =============================== SCAN ===============================
        const int b = blockIdx.x;
        if (tid >= 128) {   // dummy warps: match barrier count (1 + 2*992)
            for (int k = 0; k < 1 + (T_SEQ - WIN); ++k) __syncthreads();
            return;
        }
        float* p_bufP = pool;          // [2][2][64]
        float* eA_sh  = pool + 256;
        float* eB_sh  = pool + 320;
        float* sB_sh  = pool + 384;
        float* cnewA  = pool + 448;
        float* cnewB  = pool + 512;
        float (*Ccs)[68] = (float(*)[68])(pool + 576);

        const int warp = tid >> 5;
        const int lane = tid & 31;
        const int h    = lane >> 4;                 // half 0/1
        const int i    = (lane & 15) | (warp << 4); // row & column 0..63
        const int rb   = h << 5;

        uint64_t CrowP[16];
#pragma unroll
        for (int k = 0; k < 16; k++) {
            int j0 = rb + 2 * k;
            float x0 = (j0     == i) ? 1.f : 0.f;
            float x1 = (j0 + 1 == i) ? 1.f : 0.f;
            CrowP[k] = ((uint64_t)__float_as_uint(x1) << 32) | __float_as_uint(x0);
        }
        for (int r = rb; r < rb + 32; r++) Ccs[i][r] = (r == i) ? 1.f : 0.f;

        if (h == 0) {
            cnewA[i] = (i == 62) ? 1.f : 0.f;
            cnewB[i] = (i == 63) ? 1.f : 0.f;
            p_bufP[i]      = g_P[((size_t)b * T_SEQ + WIN)     * WIN + i];
            p_bufP[64 + i] = g_P[((size_t)b * T_SEQ + WIN + 1) * WIN + i];
        }
        __syncthreads();

        float* gC = g_C + (size_t)b * T_SEQ * WIN;
        const float* gP = g_P + (size_t)b * T_SEQ * WIN;

        for (int t0 = WIN; t0 < T_SEQ; t0 += 2) {
            const int it  = (t0 - WIN) >> 1;
            const int cur = it & 1, nxt = cur ^ 1;
            const int slotPA = (t0 - 2) & (WIN - 1);
            const int slotPB = (t0 - 1) & (WIN - 1);
            const int slotA  = t0 & (WIN - 1);
            const int slotB  = (t0 + 1) & (WIN - 1);

            float pnC = 0.f, pnD = 0.f;
            if (h == 0) {
                int tC = (t0 + 2 < T_SEQ) ? t0 + 2 : T_SEQ - 1;
                int tD = (t0 + 3 < T_SEQ) ? t0 + 3 : T_SEQ - 1;
                pnC = gP[(size_t)tC * WIN + i];
                pnD = gP[(size_t)tD * WIN + i];
            }

            if (i == slotPA) {
                const ulonglong2* cn = (const ulonglong2*)&cnewA[rb];
#pragma unroll
                for (int k = 0; k < 8; k++) {
                    ulonglong2 v = cn[k];
                    CrowP[2 * k] = v.x; CrowP[2 * k + 1] = v.y;
                }
            }
            if (i == slotPB) {
                const ulonglong2* cn = (const ulonglong2*)&cnewB[rb];
#pragma unroll
                for (int k = 0; k < 8; k++) {
                    ulonglong2 v = cn[k];
                    CrowP[2 * k] = v.x; CrowP[2 * k + 1] = v.y;
                }
            }

            const ulonglong2* pa = (const ulonglong2*)&p_bufP[cur * 128 + rb];
            const ulonglong2* pb = (const ulonglong2*)&p_bufP[cur * 128 + 64 + rb];
            uint64_t a0 = 0, a1 = 0, b0 = 0, b1 = 0;
#pragma unroll
            for (int k = 0; k < 8; k++) {
                ulonglong2 pva = pa[k];
                ulonglong2 pvb = pb[k];
                fma2(a0, CrowP[2 * k],     pva.x);
                fma2(a1, CrowP[2 * k + 1], pva.y);
                fma2(b0, CrowP[2 * k],     pvb.x);
                fma2(b1, CrowP[2 * k + 1], pvb.y);
            }
            add2(a0, a1); add2(b0, b1);
            float sigA = lo2(a0) + hi2(a0);
            float sigB = lo2(b0) + hi2(b0);
            sigA += __shfl_xor_sync(0xffffffffu, sigA, 16);
            sigB += __shfl_xor_sync(0xffffffffu, sigB, 16);
            const float eAo = ex2f(sigA);
            const float eBo = ex2f(sigB);
            if (h == 0) {
                eA_sh[i] = eAo;
                eB_sh[i] = eBo;
                sB_sh[i] = sigB;
            }
            __syncthreads();

            const ulonglong2* ev = (const ulonglong2*)&eA_sh[rb];
            const ulonglong2* sv = (const ulonglong2*)&sB_sh[rb];
            const ulonglong2* cv = (const ulonglong2*)&Ccs[i][rb];
            uint64_t dacc0 = 0, dacc1 = 0, uacc0 = 0, uacc1 = 0, sacc0 = 0, sacc1 = 0;
#pragma unroll
            for (int k = 0; k < 4; k++) {
                ulonglong2 e2a = ev[2 * k];
                ulonglong2 e2b = ev[2 * k + 1];
                ulonglong2 c2a = cv[2 * k];
                ulonglong2 c2b = cv[2 * k + 1];
                ulonglong2 s2a = sv[2 * k];
                ulonglong2 s2b = sv[2 * k + 1];
                add2(dacc0, e2a.x); add2(dacc1, e2a.y);
                add2(dacc0, e2b.x); add2(dacc1, e2b.y);
                fma2(uacc0, e2a.x, c2a.x); fma2(uacc1, e2a.y, c2a.y);
                fma2(uacc0, e2b.x, c2b.x); fma2(uacc1, e2b.y, c2b.y);
                fma2(sacc0, e2a.x, s2a.x); fma2(sacc1, e2a.y, s2a.y);
                fma2(sacc0, e2b.x, s2b.x); fma2(sacc1, e2b.y, s2b.y);
            }
            add2(dacc0, dacc1); add2(uacc0, uacc1); add2(sacc0, sacc1);
            float dA  = lo2(dacc0) + hi2(dacc0);
            float uA  = lo2(uacc0) + hi2(uacc0);
            float SAB = lo2(sacc0) + hi2(sacc0);
            dA  += __shfl_xor_sync(0xffffffffu, dA, 16);
            uA  += __shfl_xor_sync(0xffffffffu, uA, 16);
            SAB += __shfl_xor_sync(0xffffffffu, SAB, 16);

            const float invA = rcpf(dA + 1.f);
            const float cA_i = invA * uA;
            const float ePr  = ex2f(invA * SAB);

            if ((slotA >> 5) == h) Ccs[i][slotA] = cA_i;
            const float eB_slotA = eB_sh[slotA];

            const ulonglong2* ebv = (const ulonglong2*)&eB_sh[rb];
            uint64_t db0 = 0, db1 = 0, ub0 = 0, ub1 = 0;
#pragma unroll
            for (int k = 0; k < 4; k++) {
                ulonglong2 e2a = ebv[2 * k];
                ulonglong2 e2b = ebv[2 * k + 1];
                ulonglong2 c2a = ((const ulonglong2*)&Ccs[i][rb])[2 * k];
                ulonglong2 c2b = ((const ulonglong2*)&Ccs[i][rb])[2 * k + 1];
                add2(db0, e2a.x); add2(db1, e2a.y);
                add2(db0, e2b.x); add2(db1, e2b.y);
                fma2(ub0, e2a.x, c2a.x); fma2(ub1, e2a.y, c2a.y);
                fma2(ub0, e2b.x, c2b.x); fma2(ub1, e2b.y, c2b.y);
            }
            add2(db0, db1); add2(ub0, ub1);
            float dB = lo2(db0) + hi2(db0);
            float uB = lo2(ub0) + hi2(ub0);
            dB += __shfl_xor_sync(0xffffffffu, dB, 16);
            uB += __shfl_xor_sync(0xffffffffu, uB, 16);

            const float invB = rcpf(dB - eB_slotA + ePr + 1.f);
            const float cB_i = invB * (uB + (ePr - eB_slotA) * cA_i);

            if ((slotB >> 5) == h) Ccs[i][slotB] = cB_i;
            if (h == 0) {
                cnewA[i] = cA_i;
                cnewB[i] = cB_i;
                gC[(size_t)t0 * WIN + i]       = cA_i;
                gC[(size_t)(t0 + 1) * WIN + i] = cB_i;
                p_bufP[nxt * 128 + i]      = pnC;
                p_bufP[nxt * 128 + 64 + i] = pnD;
            }
            __syncthreads();

            // publish completed 64-blocks (every 32 iterations)
            if (tid == 0 && (((t0 + 2) & 63) == 0)) {
                __threadfence();
                *(volatile int*)&g_prog[b] = (t0 + 2) >> 6;
            }
        }
        return;
    }

    // ============================== WORKER ==============================
    float (*Cs)[68] = (float(*)[68])pool;            // 4352 floats
    float (*Fs)[68] = (float(*)[68])(pool + 4352);   // 4352 floats
    float* w_mu = pool + 8704;
    float* w_rs = pool + 8768;

    const int wid = blockIdx.x - BATCH;
    const int ty = tid >> 4, tx = tid & 15;
    const int r0 = ty * 4, c0l = tx * 4;

    for (int tsel = 0; tsel < 2; ++tsel) {
        const int tile = wid + tsel * NWORK;
        if (tile >= NTILE) break;
        const int m = tile >> 3;
        const int bq = tile & 7;
        const int t0 = m * WIN;
        const size_t rowbase = (size_t)bq * T_SEQ + t0;

        if (m > 0) {
            if (tid == 0) {
                while (*(volatile int*)&g_prog[bq] < m + 1) __nanosleep(256);
            }
            __syncthreads();
            __threadfence();
            // load C tile (64 rows x 64 coeffs), transposed
#pragma unroll
            for (int l = 0; l < 4; l++) {
                int s = tid + l * 256;
                int r = s >> 4, j4 = (s & 15) * 4;
                float4 c = *(const float4*)(g_C + (rowbase + r) * WIN + j4);
                Cs[j4 + 0][r] = c.x; Cs[j4 + 1][r] = c.y;
                Cs[j4 + 2][r] = c.z; Cs[j4 + 3][r] = c.w;
            }
            __syncthreads();
        }

        float sAcc[4]  = {0.f, 0.f, 0.f, 0.f};
        float ssAcc[4] = {0.f, 0.f, 0.f, 0.f};

        for (int d0 = 0; d0 < DMODEL; d0 += 64) {
            float4 v4[4];
            if (m > 0) {
#pragma unroll
                for (int l = 0; l < 4; l++) {
                    int s = tid + l * 256;
                    int j = s >> 4, c4 = (s & 15) * 4;
                    *(float4*)&Fs[j][c4] =
                        *(const float4*)(feat + ((size_t)bq * T_SEQ + j) * DMODEL + d0 + c4);
                }
                __syncthreads();
                float acc[4][4];
#pragma unroll
                for (int ii = 0; ii < 4; ii++)
#pragma unroll
                    for (int jj = 0; jj < 4; jj++) acc[ii][jj] = 0.f;
#pragma unroll 8
                for (int k = 0; k < WIN; k++) {
                    float a0 = Cs[k][r0], a1 = Cs[k][r0 + 1];
                    float a2 = Cs[k][r0 + 2], a3 = Cs[k][r0 + 3];
                    float4 bb = *(float4*)&Fs[k][c0l];
                    acc[0][0] = fmaf(a0, bb.x, acc[0][0]);
                    acc[0][1] = fmaf(a0, bb.y, acc[0][1]);
                    acc[0][2] = fmaf(a0, bb.z, acc[0][2]);
                    acc[0][3] = fmaf(a0, bb.w, acc[0][3]);
                    acc[1][0] = fmaf(a1, bb.x, acc[1][0]);
                    acc[1][1] = fmaf(a1, bb.y, acc[1][1]);
                    acc[1][2] = fmaf(a1, bb.z, acc[1][2]);
                    acc[1][3] = fmaf(a1, bb.w, acc[1][3]);
                    acc[2][0] = fmaf(a2, bb.x, acc[2][0]);
                    acc[2][1] = fmaf(a2, bb.y, acc[2][1]);
                    acc[2][2] = fmaf(a2, bb.z, acc[2][2]);
                    acc[2][3] = fmaf(a2, bb.w, acc[2][3]);
                    acc[3][0] = fmaf(a3, bb.x, acc[3][0]);
                    acc[3][1] = fmaf(a3, bb.y, acc[3][1]);
                    acc[3][2] = fmaf(a3, bb.z, acc[3][2]);
                    acc[3][3] = fmaf(a3, bb.w, acc[3][3]);
                }
#pragma unroll
                for (int ii = 0; ii < 4; ii++)
                    v4[ii] = make_float4(acc[ii][0], acc[ii][1], acc[ii][2], acc[ii][3]);
                __syncthreads();   // before next chunk overwrites Fs
            } else {
#pragma unroll
                for (int ii = 0; ii < 4; ii++)
                    v4[ii] = *(const float4*)(feat + (rowbase + r0 + ii) * DMODEL + d0 + c0l);
            }

#pragma unroll
            for (int ii = 0; ii < 4; ii++) {
                const float4 f = *(const float4*)(feat + (rowbase + r0 + ii) * DMODEL + d0 + c0l);
                float y0 = tanhf(v4[ii].x) * f.x + f.x;
                float y1 = tanhf(v4[ii].y) * f.y + f.y;
                float y2 = tanhf(v4[ii].z) * f.z + f.z;
                float y3 = tanhf(v4[ii].w) * f.w + f.w;
                *(float4*)(out + (rowbase + r0 + ii) * DMODEL + d0 + c0l) =
                    make_float4(y0, y1, y2, y3);
                sAcc[ii]  += (y0 + y1) + (y2 + y3);
                ssAcc[ii] += (y0 * y0 + y1 * y1) + (y2 * y2 + y3 * y3);
            }
        }

        // reduce row sums over the 16 tx-lanes
#pragma unroll
        for (int o = 1; o < 16; o <<= 1) {
#pragma unroll
            for (int ii = 0; ii < 4; ii++) {
                sAcc[ii]  += __shfl_xor_sync(0xffffffffu, sAcc[ii], o);
                ssAcc[ii] += __shfl_xor_sync(0xffffffffu, ssAcc[ii], o);
            }
        }
        if (tx == 0) {
#pragma unroll
            for (int ii = 0; ii < 4; ii++) {
                float mu  = sAcc[ii] * (1.f / DMODEL);
                float var = ssAcc[ii] * (1.f / DMODEL) - mu * mu;
                w_mu[r0 + ii] = mu;
                w_rs[r0 + ii] = rsqrtf(var + 1e-5f);
            }
        }
        __syncthreads();

        // pass 2: normalize in place (out tile is L2-hot)
        for (int idx = tid; idx < WIN * (DMODEL / 4); idx += 256) {
            int r  = idx >> 8;
            int c4 = (idx & 255) << 2;
            float* yp = out + (rowbase + r) * DMODEL + c4;
            float4 y = *(float4*)yp;
            const float mu = w_mu[r], rs = w_rs[r];
            float4 g4 = *(const float4*)(lng + c4);
            float4 b4 = *(const float4*)(lnb + c4);
            y.x = (y.x - mu) * rs * g4.x + b4.x;
            y.y = (y.y - mu) * rs * g4.y + b4.y;
            y.z = (y.z - mu) * rs * g4.z + b4.z;
            y.w = (y.w - mu) * rs * g4.w + b4.w;
            *(float4*)yp = y;
        }
        __syncthreads();   // before smem reuse by next tile
    }
}

// ---------------------------------------------------------------------------
extern "C" void kernel_launch(void* const* d_in, const int* in_sizes, int n_in,
                              void* d_out, int out_size)
{
    const float* feature = (const float*)d_in[0];
    const float* wq_w    = (const float*)d_in[1];
    const float* wq_b    = (const float*)d_in[2];
    const float* w2_w    = (const float*)d_in[3];
    // d_in[4] = w2_b: cancels by softmax shift-invariance
    const float* ln_g    = (const float*)d_in[5];
    const float* ln_b    = (const float*)d_in[6];
    float* out = (float*)d_out;

    bias_p_kernel<<<BATCH, 256>>>(feature, wq_b, w2_w);   // also zeroes g_prog
    m_kernel<<<dim3(8, BATCH), 256>>>(wq_w, w2_w, feature);
    p_kernel<<<dim3(16, BATCH), 256>>>(feature);
    fused_kernel<<<BATCH + NWORK, 256>>>(feature, ln_g, ln_b, out);
}